// round 7
// baseline (speedup 1.0000x reference)
#include <cuda_runtime.h>
#include <cstdint>
#include <cstddef>

#define NN 2048
#define BB 4
#define HH 8
#define HDIM 32
#define CC 256

// Scratch (allocation-free rule: __device__ globals)
__device__ float g_qkv[(size_t)BB * 3 * CC * NN];  // [4][768][2048]
__device__ float g_att[(size_t)BB * CC * NN];      // [4][256][2048]

// ---------------------------------------------------------------------------
// tf32 / math helpers
// ---------------------------------------------------------------------------
__device__ __forceinline__ uint32_t f2tf(float x) {
    uint32_t r;
    asm("cvt.rna.tf32.f32 %0, %1;" : "=r"(r) : "f"(x));
    return r;
}

__device__ __forceinline__ float ex2(float x) {
    float r;
    asm("ex2.approx.f32 %0, %1;" : "=f"(r) : "f"(x));
    return r;
}

__device__ __forceinline__ void mma_tf32(float c[4],
    uint32_t a0, uint32_t a1, uint32_t a2, uint32_t a3,
    uint32_t b0, uint32_t b1)
{
    asm volatile(
        "mma.sync.aligned.m16n8k8.row.col.f32.tf32.tf32.f32 "
        "{%0,%1,%2,%3}, {%4,%5,%6,%7}, {%8,%9}, {%0,%1,%2,%3};\n"
        : "+f"(c[0]), "+f"(c[1]), "+f"(c[2]), "+f"(c[3])
        : "r"(a0), "r"(a1), "r"(a2), "r"(a3), "r"(b0), "r"(b1));
}

// ---------------------------------------------------------------------------
// tf32 GEMM: Y[b][m][n] = sum_k W[m][k] * X[b][k][n]   (N fixed = 2048)
// 256 threads (8 warps, 4m x 2n). Tile 128m x 128n, BK=16, double-buffered.
// Warp tile 32m x 64n: 2 m-frags x 8 n-frags = 32 mma per k-tile per warp.
// A-frag LDS amortized over 8 n-frags -> 1.5 LDS/mma.
// ---------------------------------------------------------------------------
#define ASTR 136
#define BSTR 136

__global__ __launch_bounds__(256) void gemm_tf32_kernel(
    const float* __restrict__ W, const float* __restrict__ X,
    float* __restrict__ Y, int M, int K)
{
    __shared__ __align__(16) uint32_t As[2][16][ASTR];
    __shared__ __align__(16) uint32_t Bs[2][16][BSTR];

    const int b  = blockIdx.z;
    const int m0 = blockIdx.y * 128;
    const int n0 = blockIdx.x * 128;
    const float* Xb = X + (size_t)b * K * NN;
    float*       Yb = Y + (size_t)b * M * NN;

    const int tid  = threadIdx.x;
    const int warp = tid >> 5;
    const int lane = tid & 31;
    const int g    = lane >> 2;
    const int l4   = lane & 3;
    const int wm   = (warp >> 1) * 32;   // 0/32/64/96
    const int wn   = (warp & 1) * 64;    // 0/64

    float acc[2][8][4];
    #pragma unroll
    for (int mf = 0; mf < 2; mf++)
        #pragma unroll
        for (int nf = 0; nf < 8; nf++)
            #pragma unroll
            for (int j = 0; j < 4; j++) acc[mf][nf][j] = 0.f;

    // A: 128 rows x 16 k = 512 float4, 2/thread. B: 16 x 128 = 512 float4, 2/thread.
    float4 la[2], lb[2];

    #pragma unroll
    for (int j = 0; j < 2; j++) {
        const int idx = tid + j * 256;
        la[j] = *(const float4*)&W[(size_t)(m0 + (idx >> 2)) * K + (idx & 3) * 4];
        lb[j] = *(const float4*)&Xb[(size_t)(idx >> 5) * NN + n0 + (idx & 31) * 4];
    }

    #pragma unroll
    for (int j = 0; j < 2; j++) {
        const int idx = tid + j * 256;
        const int row = idx >> 2, q = idx & 3;
        As[0][4 * q + 0][row] = f2tf(la[j].x);
        As[0][4 * q + 1][row] = f2tf(la[j].y);
        As[0][4 * q + 2][row] = f2tf(la[j].z);
        As[0][4 * q + 3][row] = f2tf(la[j].w);
        uint4 u = make_uint4(f2tf(lb[j].x), f2tf(lb[j].y), f2tf(lb[j].z), f2tf(lb[j].w));
        *(uint4*)&Bs[0][idx >> 5][(idx & 31) * 4] = u;
    }
    __syncthreads();

    const int KT = K >> 4;
    for (int kt = 0; kt < KT; kt++) {
        const int cur = kt & 1, nxt = cur ^ 1;

        if (kt + 1 < KT) {
            const int k0 = (kt + 1) * 16;
            #pragma unroll
            for (int j = 0; j < 2; j++) {
                const int idx = tid + j * 256;
                la[j] = *(const float4*)&W[(size_t)(m0 + (idx >> 2)) * K + k0 + (idx & 3) * 4];
                lb[j] = *(const float4*)&Xb[(size_t)(k0 + (idx >> 5)) * NN + n0 + (idx & 31) * 4];
            }
        }

        #pragma unroll
        for (int kk = 0; kk < 2; kk++) {
            const int kb = kk * 8;
            uint32_t af[2][4];
            #pragma unroll
            for (int mf = 0; mf < 2; mf++) {
                af[mf][0] = As[cur][kb + l4][wm + mf * 16 + g];
                af[mf][1] = As[cur][kb + l4][wm + mf * 16 + g + 8];
                af[mf][2] = As[cur][kb + l4 + 4][wm + mf * 16 + g];
                af[mf][3] = As[cur][kb + l4 + 4][wm + mf * 16 + g + 8];
            }
            #pragma unroll
            for (int nf = 0; nf < 8; nf++) {
                const int nn = wn + nf * 8 + g;
                uint32_t b0 = Bs[cur][kb + l4][nn];
                uint32_t b1 = Bs[cur][kb + l4 + 4][nn];
                #pragma unroll
                for (int mf = 0; mf < 2; mf++)
                    mma_tf32(acc[mf][nf], af[mf][0], af[mf][1], af[mf][2], af[mf][3], b0, b1);
            }
        }

        if (kt + 1 < KT) {
            #pragma unroll
            for (int j = 0; j < 2; j++) {
                const int idx = tid + j * 256;
                const int row = idx >> 2, q = idx & 3;
                As[nxt][4 * q + 0][row] = f2tf(la[j].x);
                As[nxt][4 * q + 1][row] = f2tf(la[j].y);
                As[nxt][4 * q + 2][row] = f2tf(la[j].z);
                As[nxt][4 * q + 3][row] = f2tf(la[j].w);
                uint4 u = make_uint4(f2tf(lb[j].x), f2tf(lb[j].y), f2tf(lb[j].z), f2tf(lb[j].w));
                *(uint4*)&Bs[nxt][idx >> 5][(idx & 31) * 4] = u;
            }
            __syncthreads();
        }
    }

    #pragma unroll
    for (int mf = 0; mf < 2; mf++) {
        const size_t r0 = (size_t)(m0 + wm + mf * 16 + g) * NN;
        const size_t r1 = (size_t)(m0 + wm + mf * 16 + g + 8) * NN;
        #pragma unroll
        for (int nf = 0; nf < 8; nf++) {
            const int nn = n0 + wn + nf * 8 + 2 * l4;
            *(float2*)&Yb[r0 + nn] = make_float2(acc[mf][nf][0], acc[mf][nf][1]);
            *(float2*)&Yb[r1 + nn] = make_float2(acc[mf][nf][2], acc[mf][nf][3]);
        }
    }
}

// ---------------------------------------------------------------------------
// Flash attention, tf32 mma, no online max (scores bounded). 4 blocks/SM.
// Double-buffered K/V, register-staged prefetch, one __syncthreads per tile.
// P C-frag -> A-frag via intra-quad shuffles.
// ---------------------------------------------------------------------------
#define QSTR 72
#define VSTR 68
#define NTILES (NN / 64)

__global__ __launch_bounds__(128, 4) void flash_mma_kernel(
    const float* __restrict__ qkv, float* __restrict__ att)
{
    __shared__ __align__(16) uint32_t Qs[HDIM][QSTR];
    __shared__ __align__(16) uint32_t Ks[2][HDIM][QSTR];
    __shared__ __align__(16) uint32_t Vs[2][HDIM][VSTR];

    const int bh = blockIdx.y;
    const int b  = bh >> 3;
    const int h  = bh & 7;
    const int q0 = blockIdx.x * 64;

    const int tid  = threadIdx.x;
    const int warp = tid >> 5;
    const int lane = tid & 31;
    const int g    = lane >> 2;
    const int l4   = lane & 3;

    const float* qp = qkv + (size_t)(b * 3 * CC + h * HDIM) * NN;
    const float* kp = qp + (size_t)CC * NN;
    const float* vp = kp + (size_t)CC * NN;

    // 1/sqrt(32) * log2(e)
    const float qscale = 0.1767766952966369f * 1.4426950408889634f;

    const int ld_d  = tid >> 4;
    const int ld_jv = tid & 15;

    #pragma unroll
    for (int j = 0; j < 4; j++) {
        const int d = ld_d + 8 * j;
        float4 v = *(const float4*)&qp[(size_t)d * NN + q0 + ld_jv * 4];
        *(uint4*)&Qs[d][ld_jv * 4] = make_uint4(
            f2tf(v.x * qscale), f2tf(v.y * qscale),
            f2tf(v.z * qscale), f2tf(v.w * qscale));
    }

    float4 lk[4], lv[4];
    #pragma unroll
    for (int j = 0; j < 4; j++) {
        const int d = ld_d + 8 * j;
        lk[j] = *(const float4*)&kp[(size_t)d * NN + ld_jv * 4];
        lv[j] = *(const float4*)&vp[(size_t)d * NN + ld_jv * 4];
    }
    #pragma unroll
    for (int j = 0; j < 4; j++) {
        const int d = ld_d + 8 * j;
        *(uint4*)&Ks[0][d][ld_jv * 4] = make_uint4(f2tf(lk[j].x), f2tf(lk[j].y),
                                                   f2tf(lk[j].z), f2tf(lk[j].w));
        *(uint4*)&Vs[0][d][ld_jv * 4] = make_uint4(f2tf(lv[j].x), f2tf(lv[j].y),
                                                   f2tf(lv[j].z), f2tf(lv[j].w));
    }
    __syncthreads();

    const int qw = warp * 16;
    uint32_t qa[4][4];
    #pragma unroll
    for (int kk = 0; kk < 4; kk++) {
        qa[kk][0] = Qs[kk * 8 + l4][qw + g];
        qa[kk][1] = Qs[kk * 8 + l4][qw + g + 8];
        qa[kk][2] = Qs[kk * 8 + l4 + 4][qw + g];
        qa[kk][3] = Qs[kk * 8 + l4 + 4][qw + g + 8];
    }

    float oc[4][4];
    #pragma unroll
    for (int i = 0; i < 4; i++)
        #pragma unroll
        for (int j = 0; j < 4; j++) oc[i][j] = 0.f;
    float l0r = 0.f, l1r = 0.f;

    const int s1 = l4 >> 1;
    const int s2 = s1 + 2;
    const bool odd = (l4 & 1);

    for (int it = 0; it < NTILES; it++) {
        const int cur = it & 1, nxt = cur ^ 1;
        const bool more = (it + 1 < NTILES);

        if (more) {
            const int t0 = (it + 1) * 64;
            #pragma unroll
            for (int j = 0; j < 4; j++) {
                const int d = ld_d + 8 * j;
                lk[j] = *(const float4*)&kp[(size_t)d * NN + t0 + ld_jv * 4];
                lv[j] = *(const float4*)&vp[(size_t)d * NN + t0 + ld_jv * 4];
            }
        }

        // S = Q^T K : 16q x 64k
        float sc[8][4];
        #pragma unroll
        for (int nf = 0; nf < 8; nf++)
            #pragma unroll
            for (int j = 0; j < 4; j++) sc[nf][j] = 0.f;

        #pragma unroll
        for (int kk = 0; kk < 4; kk++) {
            #pragma unroll
            for (int nf = 0; nf < 8; nf++) {
                uint32_t b0 = Ks[cur][kk * 8 + l4][nf * 8 + g];
                uint32_t b1 = Ks[cur][kk * 8 + l4 + 4][nf * 8 + g];
                mma_tf32(sc[nf], qa[kk][0], qa[kk][1], qa[kk][2], qa[kk][3], b0, b1);
            }
        }

        // P = exp2(S); row sums off the O-mma critical path
        float ps0 = 0.f, ps1 = 0.f;
        #pragma unroll
        for (int nf = 0; nf < 8; nf++) {
            sc[nf][0] = ex2(sc[nf][0]); ps0 += sc[nf][0];
            sc[nf][1] = ex2(sc[nf][1]); ps0 += sc[nf][1];
            sc[nf][2] = ex2(sc[nf][2]); ps1 += sc[nf][2];
            sc[nf][3] = ex2(sc[nf][3]); ps1 += sc[nf][3];
        }
        ps0 += __shfl_xor_sync(0xffffffffu, ps0, 1);
        ps0 += __shfl_xor_sync(0xffffffffu, ps0, 2);
        ps1 += __shfl_xor_sync(0xffffffffu, ps1, 1);
        ps1 += __shfl_xor_sync(0xffffffffu, ps1, 2);
        l0r += ps0;
        l1r += ps1;

        // O += P * V^T; P C-frag -> A-frag via intra-quad shuffles
        #pragma unroll
        for (int kk = 0; kk < 8; kk++) {
            const uint32_t p0 = f2tf(sc[kk][0]);
            const uint32_t p1 = f2tf(sc[kk][1]);
            const uint32_t p2 = f2tf(sc[kk][2]);
            const uint32_t p3 = f2tf(sc[kk][3]);

            uint32_t t00 = __shfl_sync(0xffffffffu, p0, s1, 4);
            uint32_t t01 = __shfl_sync(0xffffffffu, p1, s1, 4);
            uint32_t t10 = __shfl_sync(0xffffffffu, p2, s1, 4);
            uint32_t t11 = __shfl_sync(0xffffffffu, p3, s1, 4);
            uint32_t t20 = __shfl_sync(0xffffffffu, p0, s2, 4);
            uint32_t t21 = __shfl_sync(0xffffffffu, p1, s2, 4);
            uint32_t t30 = __shfl_sync(0xffffffffu, p2, s2, 4);
            uint32_t t31 = __shfl_sync(0xffffffffu, p3, s2, 4);

            const uint32_t a0 = odd ? t01 : t00;
            const uint32_t a1 = odd ? t11 : t10;
            const uint32_t a2 = odd ? t21 : t20;
            const uint32_t a3 = odd ? t31 : t30;

            #pragma unroll
            for (int nf = 0; nf < 4; nf++) {
                uint32_t b0 = Vs[cur][nf * 8 + g][kk * 8 + l4];
                uint32_t b1 = Vs[cur][nf * 8 + g][kk * 8 + l4 + 4];
                mma_tf32(oc[nf], a0, a1, a2, a3, b0, b1);
            }
        }

        if (more) {
            #pragma unroll
            for (int j = 0; j < 4; j++) {
                const int d = ld_d + 8 * j;
                *(uint4*)&Ks[nxt][d][ld_jv * 4] = make_uint4(
                    f2tf(lk[j].x), f2tf(lk[j].y), f2tf(lk[j].z), f2tf(lk[j].w));
                *(uint4*)&Vs[nxt][d][ld_jv * 4] = make_uint4(
                    f2tf(lv[j].x), f2tf(lv[j].y), f2tf(lv[j].z), f2tf(lv[j].w));
            }
            __syncthreads();
        }
    }

    const float inv0 = 1.f / l0r;
    const float inv1 = 1.f / l1r;
    const size_t base = (size_t)(b * CC + h * HDIM);
    const int qg = q0 + qw + g;
    #pragma unroll
    for (int nf = 0; nf < 4; nf++) {
        const int d0 = nf * 8 + 2 * l4;
        att[(base + d0) * NN + qg]         = oc[nf][0] * inv0;
        att[(base + d0 + 1) * NN + qg]     = oc[nf][1] * inv0;
        att[(base + d0) * NN + qg + 8]     = oc[nf][2] * inv1;
        att[(base + d0 + 1) * NN + qg + 8] = oc[nf][3] * inv1;
    }
}

// ---------------------------------------------------------------------------
// kernel_launch
// ---------------------------------------------------------------------------
extern "C" void kernel_launch(void* const* d_in, const int* in_sizes, int n_in,
                              void* d_out, int out_size)
{
    const float* x      = (const float*)d_in[0];
    const float* w_qkv  = (const float*)d_in[1];
    const float* w_proj = (const float*)d_in[2];
    float* out          = (float*)d_out;
    (void)in_sizes; (void)n_in; (void)out_size;

    float* qkv = nullptr;
    float* att = nullptr;
    cudaGetSymbolAddress((void**)&qkv, g_qkv);
    cudaGetSymbolAddress((void**)&att, g_att);

    gemm_tf32_kernel<<<dim3(NN / 128, 768 / 128, BB), 256>>>(w_qkv, x, qkv, 768, CC);

    flash_mma_kernel<<<dim3(NN / 64, BB * HH), 128>>>(qkv, att);

    gemm_tf32_kernel<<<dim3(NN / 128, CC / 128, BB), 256>>>(w_proj, att, out, CC, CC);
}

// round 8
// speedup vs baseline: 1.0175x; 1.0175x over previous
#include <cuda_runtime.h>
#include <cstdint>
#include <cstddef>

#define NN 2048
#define BB 4
#define HH 8
#define HDIM 32
#define CC 256

// Scratch (allocation-free rule: __device__ globals)
__device__ float g_qkv[(size_t)BB * 3 * CC * NN];  // [4][768][2048]
__device__ float g_att[(size_t)BB * CC * NN];      // [4][256][2048]

// ---------------------------------------------------------------------------
// tf32 / math helpers
// ---------------------------------------------------------------------------
__device__ __forceinline__ uint32_t f2tf(float x) {
    uint32_t r;
    asm("cvt.rna.tf32.f32 %0, %1;" : "=r"(r) : "f"(x));
    return r;
}

__device__ __forceinline__ float ex2(float x) {
    float r;
    asm("ex2.approx.f32 %0, %1;" : "=f"(r) : "f"(x));
    return r;
}

__device__ __forceinline__ void mma_tf32(float c[4],
    uint32_t a0, uint32_t a1, uint32_t a2, uint32_t a3,
    uint32_t b0, uint32_t b1)
{
    asm volatile(
        "mma.sync.aligned.m16n8k8.row.col.f32.tf32.tf32.f32 "
        "{%0,%1,%2,%3}, {%4,%5,%6,%7}, {%8,%9}, {%0,%1,%2,%3};\n"
        : "+f"(c[0]), "+f"(c[1]), "+f"(c[2]), "+f"(c[3])
        : "r"(a0), "r"(a1), "r"(a2), "r"(a3), "r"(b0), "r"(b1));
}

__device__ __forceinline__ uint4 ldsm4(uint32_t addr) {
    uint4 r;
    asm volatile(
        "ldmatrix.sync.aligned.m8n8.x4.shared.b16 {%0,%1,%2,%3}, [%4];"
        : "=r"(r.x), "=r"(r.y), "=r"(r.z), "=r"(r.w) : "r"(addr));
    return r;
}

// ---------------------------------------------------------------------------
// tf32 GEMM (unchanged from R6): Y[b][m][n] = sum_k W[m][k] * X[b][k][n]
// 256 threads (8 warps, 4m x 2n). Tile 128m x 128n, BK=16, double-buffered.
// ---------------------------------------------------------------------------
#define ASTR 136
#define BSTR 136

__global__ __launch_bounds__(256) void gemm_tf32_kernel(
    const float* __restrict__ W, const float* __restrict__ X,
    float* __restrict__ Y, int M, int K)
{
    __shared__ __align__(16) uint32_t As[2][16][ASTR];
    __shared__ __align__(16) uint32_t Bs[2][16][BSTR];

    const int b  = blockIdx.z;
    const int m0 = blockIdx.y * 128;
    const int n0 = blockIdx.x * 128;
    const float* Xb = X + (size_t)b * K * NN;
    float*       Yb = Y + (size_t)b * M * NN;

    const int tid  = threadIdx.x;
    const int warp = tid >> 5;
    const int lane = tid & 31;
    const int g    = lane >> 2;
    const int l4   = lane & 3;
    const int wm   = (warp >> 1) * 32;
    const int wn   = (warp & 1) * 64;

    float acc[2][8][4];
    #pragma unroll
    for (int mf = 0; mf < 2; mf++)
        #pragma unroll
        for (int nf = 0; nf < 8; nf++)
            #pragma unroll
            for (int j = 0; j < 4; j++) acc[mf][nf][j] = 0.f;

    float4 la[2], lb[2];

    #pragma unroll
    for (int j = 0; j < 2; j++) {
        const int idx = tid + j * 256;
        la[j] = *(const float4*)&W[(size_t)(m0 + (idx >> 2)) * K + (idx & 3) * 4];
        lb[j] = *(const float4*)&Xb[(size_t)(idx >> 5) * NN + n0 + (idx & 31) * 4];
    }

    #pragma unroll
    for (int j = 0; j < 2; j++) {
        const int idx = tid + j * 256;
        const int row = idx >> 2, q = idx & 3;
        As[0][4 * q + 0][row] = f2tf(la[j].x);
        As[0][4 * q + 1][row] = f2tf(la[j].y);
        As[0][4 * q + 2][row] = f2tf(la[j].z);
        As[0][4 * q + 3][row] = f2tf(la[j].w);
        uint4 u = make_uint4(f2tf(lb[j].x), f2tf(lb[j].y), f2tf(lb[j].z), f2tf(lb[j].w));
        *(uint4*)&Bs[0][idx >> 5][(idx & 31) * 4] = u;
    }
    __syncthreads();

    const int KT = K >> 4;
    for (int kt = 0; kt < KT; kt++) {
        const int cur = kt & 1, nxt = cur ^ 1;

        if (kt + 1 < KT) {
            const int k0 = (kt + 1) * 16;
            #pragma unroll
            for (int j = 0; j < 2; j++) {
                const int idx = tid + j * 256;
                la[j] = *(const float4*)&W[(size_t)(m0 + (idx >> 2)) * K + k0 + (idx & 3) * 4];
                lb[j] = *(const float4*)&Xb[(size_t)(k0 + (idx >> 5)) * NN + n0 + (idx & 31) * 4];
            }
        }

        #pragma unroll
        for (int kk = 0; kk < 2; kk++) {
            const int kb = kk * 8;
            uint32_t af[2][4];
            #pragma unroll
            for (int mf = 0; mf < 2; mf++) {
                af[mf][0] = As[cur][kb + l4][wm + mf * 16 + g];
                af[mf][1] = As[cur][kb + l4][wm + mf * 16 + g + 8];
                af[mf][2] = As[cur][kb + l4 + 4][wm + mf * 16 + g];
                af[mf][3] = As[cur][kb + l4 + 4][wm + mf * 16 + g + 8];
            }
            #pragma unroll
            for (int nf = 0; nf < 8; nf++) {
                const int nn = wn + nf * 8 + g;
                uint32_t b0 = Bs[cur][kb + l4][nn];
                uint32_t b1 = Bs[cur][kb + l4 + 4][nn];
                #pragma unroll
                for (int mf = 0; mf < 2; mf++)
                    mma_tf32(acc[mf][nf], af[mf][0], af[mf][1], af[mf][2], af[mf][3], b0, b1);
            }
        }

        if (kt + 1 < KT) {
            #pragma unroll
            for (int j = 0; j < 2; j++) {
                const int idx = tid + j * 256;
                const int row = idx >> 2, q = idx & 3;
                As[nxt][4 * q + 0][row] = f2tf(la[j].x);
                As[nxt][4 * q + 1][row] = f2tf(la[j].y);
                As[nxt][4 * q + 2][row] = f2tf(la[j].z);
                As[nxt][4 * q + 3][row] = f2tf(la[j].w);
                uint4 u = make_uint4(f2tf(lb[j].x), f2tf(lb[j].y), f2tf(lb[j].z), f2tf(lb[j].w));
                *(uint4*)&Bs[nxt][idx >> 5][(idx & 31) * 4] = u;
            }
            __syncthreads();
        }
    }

    #pragma unroll
    for (int mf = 0; mf < 2; mf++) {
        const size_t r0 = (size_t)(m0 + wm + mf * 16 + g) * NN;
        const size_t r1 = (size_t)(m0 + wm + mf * 16 + g + 8) * NN;
        #pragma unroll
        for (int nf = 0; nf < 8; nf++) {
            const int nn = n0 + wn + nf * 8 + 2 * l4;
            *(float2*)&Yb[r0 + nn] = make_float2(acc[mf][nf][0], acc[mf][nf][1]);
            *(float2*)&Yb[r1 + nn] = make_float2(acc[mf][nf][2], acc[mf][nf][3]);
        }
    }
}

// ---------------------------------------------------------------------------
// Flash attention, tf32 mma, ldmatrix operand fetch (4x fewer smem-load
// instructions). K staged transposed [key][dim] (stride 36: ldmatrix rows
// hit disjoint bank quads); V stays [dim][key] (stride 68, same property).
// No online max (scores bounded). Double-buffered K/V, one sync per tile.
// ---------------------------------------------------------------------------
#define QSTR 72
#define KTSTR 36
#define VSTR 68
#define NTILES (NN / 64)

__global__ __launch_bounds__(128, 3) void flash_mma_kernel(
    const float* __restrict__ qkv, float* __restrict__ att)
{
    __shared__ __align__(16) uint32_t Qs[HDIM][QSTR];          // 9216 B
    __shared__ __align__(16) uint32_t Kt[2][64][KTSTR];        // 18432 B
    __shared__ __align__(16) uint32_t Vs[2][HDIM][VSTR];       // 17408 B

    const int bh = blockIdx.y;
    const int b  = bh >> 3;
    const int h  = bh & 7;
    const int q0 = blockIdx.x * 64;

    const int tid  = threadIdx.x;
    const int warp = tid >> 5;
    const int lane = tid & 31;
    const int g    = lane >> 2;
    const int l4   = lane & 3;

    const float* qp = qkv + (size_t)(b * 3 * CC + h * HDIM) * NN;
    const float* kp = qp + (size_t)CC * NN;
    const float* vp = kp + (size_t)CC * NN;

    // 1/sqrt(32) * log2(e)
    const float qscale = 0.1767766952966369f * 1.4426950408889634f;

    // Q/V staging indices (float4 along keys)
    const int ld_d  = tid >> 4;         // 0..7
    const int ld_jv = tid & 15;         // 0..15
    // K staging indices (scalar along dims, transposed store)
    const int kkey = tid & 63;          // key 0..63
    const int kdh  = tid >> 6;          // dim half 0/1

    // Load Q tile [32][64], scaled, tf32
    #pragma unroll
    for (int j = 0; j < 4; j++) {
        const int d = ld_d + 8 * j;
        float4 v = *(const float4*)&qp[(size_t)d * NN + q0 + ld_jv * 4];
        *(uint4*)&Qs[d][ld_jv * 4] = make_uint4(
            f2tf(v.x * qscale), f2tf(v.y * qscale),
            f2tf(v.z * qscale), f2tf(v.w * qscale));
    }

    // Prologue: K/V tile 0 into buffer 0
    float lk[16];
    float4 lv[4];
    #pragma unroll
    for (int i = 0; i < 16; i++)
        lk[i] = kp[(size_t)(kdh * 16 + i) * NN + kkey];
    #pragma unroll
    for (int j = 0; j < 4; j++)
        lv[j] = *(const float4*)&vp[(size_t)(ld_d + 8 * j) * NN + ld_jv * 4];

    #pragma unroll
    for (int c = 0; c < 4; c++) {
        *(uint4*)&Kt[0][kkey][kdh * 16 + c * 4] = make_uint4(
            f2tf(lk[c * 4 + 0]), f2tf(lk[c * 4 + 1]),
            f2tf(lk[c * 4 + 2]), f2tf(lk[c * 4 + 3]));
    }
    #pragma unroll
    for (int j = 0; j < 4; j++) {
        const int d = ld_d + 8 * j;
        *(uint4*)&Vs[0][d][ld_jv * 4] = make_uint4(f2tf(lv[j].x), f2tf(lv[j].y),
                                                   f2tf(lv[j].z), f2tf(lv[j].w));
    }
    __syncthreads();

    // Q^T A-fragments, resident for whole kernel
    const int qw = warp * 16;
    uint32_t qa[4][4];
    #pragma unroll
    for (int kk = 0; kk < 4; kk++) {
        qa[kk][0] = Qs[kk * 8 + l4][qw + g];
        qa[kk][1] = Qs[kk * 8 + l4][qw + g + 8];
        qa[kk][2] = Qs[kk * 8 + l4 + 4][qw + g];
        qa[kk][3] = Qs[kk * 8 + l4 + 4][qw + g + 8];
    }

    // Per-lane ldmatrix address constants (in words)
    // K: tiles [nfp: keys 2nfp*8.. / +8][dim halves 0/4]
    const int kt_row  = (lane & 7) + 8 * (lane >> 4);      // key-row within pair
    const int kt_doff = ((lane >> 3) & 1) * 4;             // dim seg 0 / 4
    const int klane_w = kt_row * KTSTR + kt_doff;
    // V: tiles [nfp: dims 2nfp*8.. / +8][key halves 0/4]
    const int vt_row  = (lane & 7) + 8 * (lane >> 4);      // dim-row within pair
    const int vt_koff = ((lane >> 3) & 1) * 4;             // key seg 0 / 4
    const int vlane_w = vt_row * VSTR + vt_koff;

    const uint32_t kt_base0 = (uint32_t)__cvta_generic_to_shared(&Kt[0][0][0]);
    const uint32_t kt_base1 = (uint32_t)__cvta_generic_to_shared(&Kt[1][0][0]);
    const uint32_t vs_base0 = (uint32_t)__cvta_generic_to_shared(&Vs[0][0][0]);
    const uint32_t vs_base1 = (uint32_t)__cvta_generic_to_shared(&Vs[1][0][0]);

    float oc[4][4];
    #pragma unroll
    for (int i = 0; i < 4; i++)
        #pragma unroll
        for (int j = 0; j < 4; j++) oc[i][j] = 0.f;
    float l0r = 0.f, l1r = 0.f;

    const int s1 = l4 >> 1;
    const int s2 = s1 + 2;
    const bool odd = (l4 & 1);

    for (int it = 0; it < NTILES; it++) {
        const int cur = it & 1, nxt = cur ^ 1;
        const bool more = (it + 1 < NTILES);
        const uint32_t ktb = (cur ? kt_base1 : kt_base0) + 4u * klane_w;
        const uint32_t vsb = (cur ? vs_base1 : vs_base0) + 4u * vlane_w;

        // Prefetch next K/V tile into registers
        if (more) {
            const int t0 = (it + 1) * 64;
            #pragma unroll
            for (int i = 0; i < 16; i++)
                lk[i] = kp[(size_t)(kdh * 16 + i) * NN + t0 + kkey];
            #pragma unroll
            for (int j = 0; j < 4; j++)
                lv[j] = *(const float4*)&vp[(size_t)(ld_d + 8 * j) * NN + t0 + ld_jv * 4];
        }

        // S = Q^T K : 16q x 64k. K B-frags via ldmatrix.x4 over Kt[key][dim].
        float sc[8][4];
        #pragma unroll
        for (int nf = 0; nf < 8; nf++)
            #pragma unroll
            for (int j = 0; j < 4; j++) sc[nf][j] = 0.f;

        #pragma unroll
        for (int kk = 0; kk < 4; kk++) {
            #pragma unroll
            for (int nfp = 0; nfp < 4; nfp++) {
                uint4 bb = ldsm4(ktb + 4u * (nfp * 16 * KTSTR + kk * 8));
                mma_tf32(sc[2 * nfp],     qa[kk][0], qa[kk][1], qa[kk][2], qa[kk][3], bb.x, bb.y);
                mma_tf32(sc[2 * nfp + 1], qa[kk][0], qa[kk][1], qa[kk][2], qa[kk][3], bb.z, bb.w);
            }
        }

        // P = exp2(S); row sums off the O-mma critical path
        float ps0 = 0.f, ps1 = 0.f;
        #pragma unroll
        for (int nf = 0; nf < 8; nf++) {
            sc[nf][0] = ex2(sc[nf][0]); ps0 += sc[nf][0];
            sc[nf][1] = ex2(sc[nf][1]); ps0 += sc[nf][1];
            sc[nf][2] = ex2(sc[nf][2]); ps1 += sc[nf][2];
            sc[nf][3] = ex2(sc[nf][3]); ps1 += sc[nf][3];
        }
        ps0 += __shfl_xor_sync(0xffffffffu, ps0, 1);
        ps0 += __shfl_xor_sync(0xffffffffu, ps0, 2);
        ps1 += __shfl_xor_sync(0xffffffffu, ps1, 1);
        ps1 += __shfl_xor_sync(0xffffffffu, ps1, 2);
        l0r += ps0;
        l1r += ps1;

        // O += P * V^T; P C-frag -> A-frag via intra-quad shuffles,
        // V B-frags via ldmatrix.x4 over Vs[dim][key].
        #pragma unroll
        for (int kk = 0; kk < 8; kk++) {
            const uint32_t p0 = f2tf(sc[kk][0]);
            const uint32_t p1 = f2tf(sc[kk][1]);
            const uint32_t p2 = f2tf(sc[kk][2]);
            const uint32_t p3 = f2tf(sc[kk][3]);

            uint32_t t00 = __shfl_sync(0xffffffffu, p0, s1, 4);
            uint32_t t01 = __shfl_sync(0xffffffffu, p1, s1, 4);
            uint32_t t10 = __shfl_sync(0xffffffffu, p2, s1, 4);
            uint32_t t11 = __shfl_sync(0xffffffffu, p3, s1, 4);
            uint32_t t20 = __shfl_sync(0xffffffffu, p0, s2, 4);
            uint32_t t21 = __shfl_sync(0xffffffffu, p1, s2, 4);
            uint32_t t30 = __shfl_sync(0xffffffffu, p2, s2, 4);
            uint32_t t31 = __shfl_sync(0xffffffffu, p3, s2, 4);

            const uint32_t a0 = odd ? t01 : t00;
            const uint32_t a1 = odd ? t11 : t10;
            const uint32_t a2 = odd ? t21 : t20;
            const uint32_t a3 = odd ? t31 : t30;

            #pragma unroll
            for (int nfp = 0; nfp < 2; nfp++) {
                uint4 bb = ldsm4(vsb + 4u * (nfp * 16 * VSTR + kk * 8));
                mma_tf32(oc[2 * nfp],     a0, a1, a2, a3, bb.x, bb.y);
                mma_tf32(oc[2 * nfp + 1], a0, a1, a2, a3, bb.z, bb.w);
            }
        }

        // Stage next tile into the other buffer; one sync per tile
        if (more) {
            #pragma unroll
            for (int c = 0; c < 4; c++) {
                *(uint4*)&Kt[nxt][kkey][kdh * 16 + c * 4] = make_uint4(
                    f2tf(lk[c * 4 + 0]), f2tf(lk[c * 4 + 1]),
                    f2tf(lk[c * 4 + 2]), f2tf(lk[c * 4 + 3]));
            }
            #pragma unroll
            for (int j = 0; j < 4; j++) {
                const int d = ld_d + 8 * j;
                *(uint4*)&Vs[nxt][d][ld_jv * 4] = make_uint4(
                    f2tf(lv[j].x), f2tf(lv[j].y), f2tf(lv[j].z), f2tf(lv[j].w));
            }
            __syncthreads();
        }
    }

    const float inv0 = 1.f / l0r;
    const float inv1 = 1.f / l1r;
    const size_t base = (size_t)(b * CC + h * HDIM);
    const int qg = q0 + qw + g;
    #pragma unroll
    for (int nf = 0; nf < 4; nf++) {
        const int d0 = nf * 8 + 2 * l4;
        att[(base + d0) * NN + qg]         = oc[nf][0] * inv0;
        att[(base + d0 + 1) * NN + qg]     = oc[nf][1] * inv0;
        att[(base + d0) * NN + qg + 8]     = oc[nf][2] * inv1;
        att[(base + d0 + 1) * NN + qg + 8] = oc[nf][3] * inv1;
    }
}

// ---------------------------------------------------------------------------
// kernel_launch
// ---------------------------------------------------------------------------
extern "C" void kernel_launch(void* const* d_in, const int* in_sizes, int n_in,
                              void* d_out, int out_size)
{
    const float* x      = (const float*)d_in[0];
    const float* w_qkv  = (const float*)d_in[1];
    const float* w_proj = (const float*)d_in[2];
    float* out          = (float*)d_out;
    (void)in_sizes; (void)n_in; (void)out_size;

    float* qkv = nullptr;
    float* att = nullptr;
    cudaGetSymbolAddress((void**)&qkv, g_qkv);
    cudaGetSymbolAddress((void**)&att, g_att);

    gemm_tf32_kernel<<<dim3(NN / 128, 768 / 128, BB), 256>>>(w_qkv, x, qkv, 768, CC);

    flash_mma_kernel<<<dim3(NN / 64, BB * HH), 128>>>(qkv, att);

    gemm_tf32_kernel<<<dim3(NN / 128, CC / 128, BB), 256>>>(w_proj, att, out, CC, CC);
}

// round 9
// speedup vs baseline: 1.0186x; 1.0010x over previous
#include <cuda_runtime.h>
#include <cstdint>
#include <cstddef>

#define NN 2048
#define BB 4
#define HH 8
#define HDIM 32
#define CC 256

// Scratch (allocation-free rule: __device__ globals). tf32-bit payloads.
__device__ uint32_t g_xt[(size_t)BB * CC * NN];        // x pre-converted
__device__ uint32_t g_wqkvt[768 * CC];                 // w_qkv pre-converted
__device__ uint32_t g_wprojt[CC * CC];                 // w_proj pre-converted
__device__ uint32_t g_qkv[(size_t)BB * 3 * CC * NN];   // qkv (tf32 bits)
__device__ uint32_t g_att[(size_t)BB * CC * NN];       // attention out (tf32 bits)

// ---------------------------------------------------------------------------
// helpers
// ---------------------------------------------------------------------------
__device__ __forceinline__ uint32_t f2tf(float x) {
    uint32_t r;
    asm("cvt.rna.tf32.f32 %0, %1;" : "=r"(r) : "f"(x));
    return r;
}

__device__ __forceinline__ float ex2(float x) {
    float r;
    asm("ex2.approx.f32 %0, %1;" : "=f"(r) : "f"(x));
    return r;
}

__device__ __forceinline__ void mma_tf32(float c[4],
    uint32_t a0, uint32_t a1, uint32_t a2, uint32_t a3,
    uint32_t b0, uint32_t b1)
{
    asm volatile(
        "mma.sync.aligned.m16n8k8.row.col.f32.tf32.tf32.f32 "
        "{%0,%1,%2,%3}, {%4,%5,%6,%7}, {%8,%9}, {%0,%1,%2,%3};\n"
        : "+f"(c[0]), "+f"(c[1]), "+f"(c[2]), "+f"(c[3])
        : "r"(a0), "r"(a1), "r"(a2), "r"(a3), "r"(b0), "r"(b1));
}

__device__ __forceinline__ uint4 ldsm4(uint32_t addr) {
    uint4 r;
    asm volatile(
        "ldmatrix.sync.aligned.m8n8.x4.shared.b16 {%0,%1,%2,%3}, [%4];"
        : "=r"(r.x), "=r"(r.y), "=r"(r.z), "=r"(r.w) : "r"(addr));
    return r;
}

// ---------------------------------------------------------------------------
// Pre-convert fp32 -> tf32 bits (vectorized, grid-stride)
// ---------------------------------------------------------------------------
__global__ void cvt_tf32_kernel(const float4* __restrict__ src,
                                uint4* __restrict__ dst, int n4)
{
    for (int i = blockIdx.x * blockDim.x + threadIdx.x; i < n4;
         i += gridDim.x * blockDim.x) {
        float4 v = src[i];
        dst[i] = make_uint4(f2tf(v.x), f2tf(v.y), f2tf(v.z), f2tf(v.w));
    }
}

// ---------------------------------------------------------------------------
// tf32 GEMM on pre-converted inputs: Y[b][m][n] = sum_k W[m][k]*X[b][k][n]
// 256 thr (8 warps, 4m x 2n). Tile 128x128, BK=16, double-buffered.
// A staged [m][k] (str 20), B staged TRANSPOSED [n][k] (str 20);
// all fragments via ldmatrix.x4, zero cvt in the hot loop.
// ---------------------------------------------------------------------------
#define AKSTR 20
#define BKSTR 20

__global__ __launch_bounds__(256) void gemm_tf32_kernel(
    const uint32_t* __restrict__ W, const uint32_t* __restrict__ X,
    uint32_t* __restrict__ Y, int M, int K, int out_tf32)
{
    __shared__ __align__(16) uint32_t As[2][128][AKSTR];
    __shared__ __align__(16) uint32_t Bs[2][128][BKSTR];

    const int b  = blockIdx.z;
    const int m0 = blockIdx.y * 128;
    const int n0 = blockIdx.x * 128;
    const uint32_t* Xb = X + (size_t)b * K * NN;
    uint32_t*       Yb = Y + (size_t)b * M * NN;

    const int tid  = threadIdx.x;
    const int warp = tid >> 5;
    const int lane = tid & 31;
    const int g    = lane >> 2;
    const int l4   = lane & 3;
    const int wm   = (warp >> 1) * 32;
    const int wn   = (warp & 1) * 64;

    // A stage: idx = tid + j*256 -> row=idx>>2 (0..127), q=idx&3
    const int arow0 = tid >> 2, aq = tid & 3;
    // B stage: n = tid & 127, kh = tid >> 7 (k rows kh*8..kh*8+7)
    const int bn = tid & 127, kh = tid >> 7;

    float acc[2][8][4];
    #pragma unroll
    for (int mf = 0; mf < 2; mf++)
        #pragma unroll
        for (int nf = 0; nf < 8; nf++)
            #pragma unroll
            for (int j = 0; j < 4; j++) acc[mf][nf][j] = 0.f;

    uint4 la[2];
    uint32_t lb[8];

    // ldmatrix lane-address constants (words)
    const int a_lane_w = (lane & 15) * AKSTR + (lane >> 4) * 4;
    const int b_lane_w = ((lane >> 4) * 8 + (lane & 7)) * BKSTR + ((lane >> 3) & 1) * 4;
    const uint32_t as_base[2] = {
        (uint32_t)__cvta_generic_to_shared(&As[0][0][0]),
        (uint32_t)__cvta_generic_to_shared(&As[1][0][0]) };
    const uint32_t bs_base[2] = {
        (uint32_t)__cvta_generic_to_shared(&Bs[0][0][0]),
        (uint32_t)__cvta_generic_to_shared(&Bs[1][0][0]) };

    // Prologue: load k-tile 0
    #pragma unroll
    for (int j = 0; j < 2; j++) {
        const int idx = tid + j * 256;
        la[j] = *(const uint4*)&W[(size_t)(m0 + (idx >> 2)) * K + (idx & 3) * 4];
    }
    #pragma unroll
    for (int i = 0; i < 8; i++)
        lb[i] = Xb[(size_t)(kh * 8 + i) * NN + n0 + bn];

    #pragma unroll
    for (int j = 0; j < 2; j++) {
        const int idx = tid + j * 256;
        *(uint4*)&As[0][idx >> 2][(idx & 3) * 4] = la[j];
    }
    *(uint4*)&Bs[0][bn][kh * 8]     = make_uint4(lb[0], lb[1], lb[2], lb[3]);
    *(uint4*)&Bs[0][bn][kh * 8 + 4] = make_uint4(lb[4], lb[5], lb[6], lb[7]);
    __syncthreads();

    const int KT = K >> 4;
    for (int kt = 0; kt < KT; kt++) {
        const int cur = kt & 1, nxt = cur ^ 1;

        if (kt + 1 < KT) {
            const int k0 = (kt + 1) * 16;
            #pragma unroll
            for (int j = 0; j < 2; j++) {
                const int idx = tid + j * 256;
                la[j] = *(const uint4*)&W[(size_t)(m0 + (idx >> 2)) * K + k0 + (idx & 3) * 4];
            }
            #pragma unroll
            for (int i = 0; i < 8; i++)
                lb[i] = Xb[(size_t)(k0 + kh * 8 + i) * NN + n0 + bn];
        }

        const uint32_t asb = as_base[cur] + 4u * a_lane_w;
        const uint32_t bsb = bs_base[cur] + 4u * b_lane_w;

        #pragma unroll
        for (int kk = 0; kk < 2; kk++) {
            const int kb = kk * 8;
            uint4 af[2];
            #pragma unroll
            for (int mf = 0; mf < 2; mf++)
                af[mf] = ldsm4(asb + 4u * ((wm + mf * 16) * AKSTR + kb));
            #pragma unroll
            for (int p = 0; p < 4; p++) {
                uint4 bb = ldsm4(bsb + 4u * ((wn + p * 16) * BKSTR + kb));
                #pragma unroll
                for (int mf = 0; mf < 2; mf++) {
                    mma_tf32(acc[mf][2 * p],     af[mf].x, af[mf].y, af[mf].z, af[mf].w, bb.x, bb.y);
                    mma_tf32(acc[mf][2 * p + 1], af[mf].x, af[mf].y, af[mf].z, af[mf].w, bb.z, bb.w);
                }
            }
        }

        if (kt + 1 < KT) {
            #pragma unroll
            for (int j = 0; j < 2; j++) {
                const int idx = tid + j * 256;
                *(uint4*)&As[nxt][idx >> 2][(idx & 3) * 4] = la[j];
            }
            *(uint4*)&Bs[nxt][bn][kh * 8]     = make_uint4(lb[0], lb[1], lb[2], lb[3]);
            *(uint4*)&Bs[nxt][bn][kh * 8 + 4] = make_uint4(lb[4], lb[5], lb[6], lb[7]);
            __syncthreads();
        }
    }

    // Epilogue
    #pragma unroll
    for (int mf = 0; mf < 2; mf++) {
        const size_t r0 = (size_t)(m0 + wm + mf * 16 + g) * NN;
        const size_t r1 = (size_t)(m0 + wm + mf * 16 + g + 8) * NN;
        #pragma unroll
        for (int nf = 0; nf < 8; nf++) {
            const int nn = n0 + wn + nf * 8 + 2 * l4;
            uint2 u0, u1;
            if (out_tf32) {
                u0 = make_uint2(f2tf(acc[mf][nf][0]), f2tf(acc[mf][nf][1]));
                u1 = make_uint2(f2tf(acc[mf][nf][2]), f2tf(acc[mf][nf][3]));
            } else {
                u0 = make_uint2(__float_as_uint(acc[mf][nf][0]), __float_as_uint(acc[mf][nf][1]));
                u1 = make_uint2(__float_as_uint(acc[mf][nf][2]), __float_as_uint(acc[mf][nf][3]));
            }
            *(uint2*)&Yb[r0 + nn] = u0;
            *(uint2*)&Yb[r1 + nn] = u1;
        }
    }
}

// ---------------------------------------------------------------------------
// Flash attention, tf32 mma, software-pipelined:
//   O-mma(t) -> stage(t+1) -> sync -> S-mma(t+1) -> softmax(t+1)
// so O(t)+S(t+1) form one dense tensor burst. Row sums deferred to epilogue
// (thread-local partials). K/V arrive pre-tf32 (no cvt in staging).
// ---------------------------------------------------------------------------
#define QSTR 72
#define KTSTR 36
#define VSTR 68
#define NTILES (NN / 64)

__global__ __launch_bounds__(128, 3) void flash_mma_kernel(
    const uint32_t* __restrict__ qkv, uint32_t* __restrict__ att)
{
    __shared__ __align__(16) uint32_t Qs[HDIM][QSTR];          // 9216 B
    __shared__ __align__(16) uint32_t Kt[2][64][KTSTR];        // 18432 B
    __shared__ __align__(16) uint32_t Vs[2][HDIM][VSTR];       // 17408 B

    const int bh = blockIdx.y;
    const int b  = bh >> 3;
    const int h  = bh & 7;
    const int q0 = blockIdx.x * 64;

    const int tid  = threadIdx.x;
    const int warp = tid >> 5;
    const int lane = tid & 31;
    const int g    = lane >> 2;
    const int l4   = lane & 3;

    const uint32_t* qp_u = qkv + (size_t)(b * 3 * CC + h * HDIM) * NN;
    const uint32_t* kp = qp_u + (size_t)CC * NN;
    const uint32_t* vp = kp + (size_t)CC * NN;
    const float* qp = (const float*)qp_u;

    // 1/sqrt(32) * log2(e)
    const float qscale = 0.1767766952966369f * 1.4426950408889634f;

    const int ld_d  = tid >> 4;         // 0..7
    const int ld_jv = tid & 15;         // 0..15
    const int kkey = tid & 63;          // key 0..63
    const int kdh  = tid >> 6;          // dim half 0/1

    // Q tile (scale + cvt; Q is tf32-rounded float, double-round is fine)
    #pragma unroll
    for (int j = 0; j < 4; j++) {
        const int d = ld_d + 8 * j;
        float4 v = *(const float4*)&qp[(size_t)d * NN + q0 + ld_jv * 4];
        *(uint4*)&Qs[d][ld_jv * 4] = make_uint4(
            f2tf(v.x * qscale), f2tf(v.y * qscale),
            f2tf(v.z * qscale), f2tf(v.w * qscale));
    }

    // Stage K/V tile 0 (raw tf32 bits, no cvt)
    uint32_t lk[16];
    uint4 lv[4];
    #pragma unroll
    for (int i = 0; i < 16; i++)
        lk[i] = kp[(size_t)(kdh * 16 + i) * NN + kkey];
    #pragma unroll
    for (int j = 0; j < 4; j++)
        lv[j] = *(const uint4*)&vp[(size_t)(ld_d + 8 * j) * NN + ld_jv * 4];

    #pragma unroll
    for (int c = 0; c < 4; c++)
        *(uint4*)&Kt[0][kkey][kdh * 16 + c * 4] =
            make_uint4(lk[c * 4], lk[c * 4 + 1], lk[c * 4 + 2], lk[c * 4 + 3]);
    #pragma unroll
    for (int j = 0; j < 4; j++)
        *(uint4*)&Vs[0][ld_d + 8 * j][ld_jv * 4] = lv[j];
    __syncthreads();

    // Q^T A-fragments, resident
    const int qw = warp * 16;
    uint32_t qa[4][4];
    #pragma unroll
    for (int kk = 0; kk < 4; kk++) {
        qa[kk][0] = Qs[kk * 8 + l4][qw + g];
        qa[kk][1] = Qs[kk * 8 + l4][qw + g + 8];
        qa[kk][2] = Qs[kk * 8 + l4 + 4][qw + g];
        qa[kk][3] = Qs[kk * 8 + l4 + 4][qw + g + 8];
    }

    // ldmatrix lane constants
    const int klane_w = ((lane & 7) + 8 * (lane >> 4)) * KTSTR + ((lane >> 3) & 1) * 4;
    const int vlane_w = ((lane & 7) + 8 * (lane >> 4)) * VSTR + ((lane >> 3) & 1) * 4;
    const uint32_t kt_base[2] = {
        (uint32_t)__cvta_generic_to_shared(&Kt[0][0][0]),
        (uint32_t)__cvta_generic_to_shared(&Kt[1][0][0]) };
    const uint32_t vs_base[2] = {
        (uint32_t)__cvta_generic_to_shared(&Vs[0][0][0]),
        (uint32_t)__cvta_generic_to_shared(&Vs[1][0][0]) };

    float oc[4][4];
    #pragma unroll
    for (int i = 0; i < 4; i++)
        #pragma unroll
        for (int j = 0; j < 4; j++) oc[i][j] = 0.f;
    float sl0 = 0.f, sl1 = 0.f;      // deferred row-sum partials

    const int s1 = l4 >> 1;
    const int s2 = s1 + 2;
    const bool odd = (l4 & 1);

    // --- S(0) + softmax(0) ---
    float sc[8][4];
    {
        const uint32_t ktb = kt_base[0] + 4u * klane_w;
        #pragma unroll
        for (int nf = 0; nf < 8; nf++)
            #pragma unroll
            for (int j = 0; j < 4; j++) sc[nf][j] = 0.f;
        #pragma unroll
        for (int kk = 0; kk < 4; kk++)
            #pragma unroll
            for (int nfp = 0; nfp < 4; nfp++) {
                uint4 bb = ldsm4(ktb + 4u * (nfp * 16 * KTSTR + kk * 8));
                mma_tf32(sc[2 * nfp],     qa[kk][0], qa[kk][1], qa[kk][2], qa[kk][3], bb.x, bb.y);
                mma_tf32(sc[2 * nfp + 1], qa[kk][0], qa[kk][1], qa[kk][2], qa[kk][3], bb.z, bb.w);
            }
        #pragma unroll
        for (int nf = 0; nf < 8; nf++) {
            sc[nf][0] = ex2(sc[nf][0]); sl0 += sc[nf][0];
            sc[nf][1] = ex2(sc[nf][1]); sl0 += sc[nf][1];
            sc[nf][2] = ex2(sc[nf][2]); sl1 += sc[nf][2];
            sc[nf][3] = ex2(sc[nf][3]); sl1 += sc[nf][3];
        }
    }

    for (int it = 0; it < NTILES; it++) {
        const int cur = it & 1, nxt = cur ^ 1;
        const bool more = (it + 1 < NTILES);

        // Prefetch tile it+1 (regs)
        if (more) {
            const int t0 = (it + 1) * 64;
            #pragma unroll
            for (int i = 0; i < 16; i++)
                lk[i] = kp[(size_t)(kdh * 16 + i) * NN + t0 + kkey];
            #pragma unroll
            for (int j = 0; j < 4; j++)
                lv[j] = *(const uint4*)&vp[(size_t)(ld_d + 8 * j) * NN + t0 + ld_jv * 4];
        }

        // --- O-mma(it): transpose P + V ldsm + 32 mma ---
        const uint32_t vsb = vs_base[cur] + 4u * vlane_w;
        #pragma unroll
        for (int kk = 0; kk < 8; kk++) {
            const uint32_t p0 = f2tf(sc[kk][0]);
            const uint32_t p1 = f2tf(sc[kk][1]);
            const uint32_t p2 = f2tf(sc[kk][2]);
            const uint32_t p3 = f2tf(sc[kk][3]);

            uint32_t t00 = __shfl_sync(0xffffffffu, p0, s1, 4);
            uint32_t t01 = __shfl_sync(0xffffffffu, p1, s1, 4);
            uint32_t t10 = __shfl_sync(0xffffffffu, p2, s1, 4);
            uint32_t t11 = __shfl_sync(0xffffffffu, p3, s1, 4);
            uint32_t t20 = __shfl_sync(0xffffffffu, p0, s2, 4);
            uint32_t t21 = __shfl_sync(0xffffffffu, p1, s2, 4);
            uint32_t t30 = __shfl_sync(0xffffffffu, p2, s2, 4);
            uint32_t t31 = __shfl_sync(0xffffffffu, p3, s2, 4);

            const uint32_t a0 = odd ? t01 : t00;
            const uint32_t a1 = odd ? t11 : t10;
            const uint32_t a2 = odd ? t21 : t20;
            const uint32_t a3 = odd ? t31 : t30;

            #pragma unroll
            for (int nfp = 0; nfp < 2; nfp++) {
                uint4 bb = ldsm4(vsb + 4u * (nfp * 16 * VSTR + kk * 8));
                mma_tf32(oc[2 * nfp],     a0, a1, a2, a3, bb.x, bb.y);
                mma_tf32(oc[2 * nfp + 1], a0, a1, a2, a3, bb.z, bb.w);
            }
        }

        if (more) {
            // Stage tile it+1
            #pragma unroll
            for (int c = 0; c < 4; c++)
                *(uint4*)&Kt[nxt][kkey][kdh * 16 + c * 4] =
                    make_uint4(lk[c * 4], lk[c * 4 + 1], lk[c * 4 + 2], lk[c * 4 + 3]);
            #pragma unroll
            for (int j = 0; j < 4; j++)
                *(uint4*)&Vs[nxt][ld_d + 8 * j][ld_jv * 4] = lv[j];
            __syncthreads();

            // --- S-mma(it+1) ---
            const uint32_t ktb = kt_base[nxt] + 4u * klane_w;
            #pragma unroll
            for (int nf = 0; nf < 8; nf++)
                #pragma unroll
                for (int j = 0; j < 4; j++) sc[nf][j] = 0.f;
            #pragma unroll
            for (int kk = 0; kk < 4; kk++)
                #pragma unroll
                for (int nfp = 0; nfp < 4; nfp++) {
                    uint4 bb = ldsm4(ktb + 4u * (nfp * 16 * KTSTR + kk * 8));
                    mma_tf32(sc[2 * nfp],     qa[kk][0], qa[kk][1], qa[kk][2], qa[kk][3], bb.x, bb.y);
                    mma_tf32(sc[2 * nfp + 1], qa[kk][0], qa[kk][1], qa[kk][2], qa[kk][3], bb.z, bb.w);
                }

            // --- softmax(it+1), sums deferred ---
            #pragma unroll
            for (int nf = 0; nf < 8; nf++) {
                sc[nf][0] = ex2(sc[nf][0]); sl0 += sc[nf][0];
                sc[nf][1] = ex2(sc[nf][1]); sl0 += sc[nf][1];
                sc[nf][2] = ex2(sc[nf][2]); sl1 += sc[nf][2];
                sc[nf][3] = ex2(sc[nf][3]); sl1 += sc[nf][3];
            }
        }
    }

    // Epilogue: reduce row sums, normalize, store tf32 bits
    sl0 += __shfl_xor_sync(0xffffffffu, sl0, 1);
    sl0 += __shfl_xor_sync(0xffffffffu, sl0, 2);
    sl1 += __shfl_xor_sync(0xffffffffu, sl1, 1);
    sl1 += __shfl_xor_sync(0xffffffffu, sl1, 2);
    const float inv0 = 1.f / sl0;
    const float inv1 = 1.f / sl1;
    const size_t base = (size_t)(b * CC + h * HDIM);
    const int qg = q0 + qw + g;
    #pragma unroll
    for (int nf = 0; nf < 4; nf++) {
        const int d0 = nf * 8 + 2 * l4;
        att[(base + d0) * NN + qg]         = f2tf(oc[nf][0] * inv0);
        att[(base + d0 + 1) * NN + qg]     = f2tf(oc[nf][1] * inv0);
        att[(base + d0) * NN + qg + 8]     = f2tf(oc[nf][2] * inv1);
        att[(base + d0 + 1) * NN + qg + 8] = f2tf(oc[nf][3] * inv1);
    }
}

// ---------------------------------------------------------------------------
// kernel_launch
// ---------------------------------------------------------------------------
extern "C" void kernel_launch(void* const* d_in, const int* in_sizes, int n_in,
                              void* d_out, int out_size)
{
    const float* x      = (const float*)d_in[0];
    const float* w_qkv  = (const float*)d_in[1];
    const float* w_proj = (const float*)d_in[2];
    uint32_t* out       = (uint32_t*)d_out;
    (void)in_sizes; (void)n_in; (void)out_size;

    uint32_t *xt, *wq, *wp, *qkv, *att;
    cudaGetSymbolAddress((void**)&xt,  g_xt);
    cudaGetSymbolAddress((void**)&wq,  g_wqkvt);
    cudaGetSymbolAddress((void**)&wp,  g_wprojt);
    cudaGetSymbolAddress((void**)&qkv, g_qkv);
    cudaGetSymbolAddress((void**)&att, g_att);

    // Pre-convert inputs to tf32 bits
    const int nx4 = (BB * CC * NN) / 4;
    cvt_tf32_kernel<<<(nx4 + 255) / 256, 256>>>((const float4*)x, (uint4*)xt, nx4);
    const int nwq4 = (768 * CC) / 4;
    cvt_tf32_kernel<<<(nwq4 + 255) / 256, 256>>>((const float4*)w_qkv, (uint4*)wq, nwq4);
    const int nwp4 = (CC * CC) / 4;
    cvt_tf32_kernel<<<(nwp4 + 255) / 256, 256>>>((const float4*)w_proj, (uint4*)wp, nwp4);

    // QKV GEMM (emit tf32 bits)
    gemm_tf32_kernel<<<dim3(NN / 128, 768 / 128, BB), 256>>>(wq, xt, qkv, 768, CC, 1);

    // Flash attention (emit tf32 bits)
    flash_mma_kernel<<<dim3(NN / 64, BB * HH), 128>>>(qkv, att);

    // Proj GEMM (emit fp32)
    gemm_tf32_kernel<<<dim3(NN / 128, CC / 128, BB), 256>>>(wp, att, out, CC, CC, 0);
}